// round 2
// baseline (speedup 1.0000x reference)
#include <cuda_runtime.h>
#include <math.h>

// Problem constants
#define BB 32
#define SS 2048
#define DD 1024
#define UU 1024

// d_out layout: [context (32*1024)][attention_weights (32*2048)][coverage_out (32*2048)]
#define CTX_OFF 0
#define ATT_OFF (BB * DD)
#define COV_OFF (BB * DD + BB * SS)

typedef unsigned long long ull;

// Scratch (allocation-free per harness rules)
__device__ float g_projdec[BB * UU];
__device__ float g_score[BB * SS];

// ---- packed f32x2 helpers (Blackwell; ptxas won't auto-fuse these) ----
__device__ __forceinline__ ull pk2(float lo, float hi) {
    ull r;
    asm("mov.b64 %0, {%1, %2};" : "=l"(r) : "f"(lo), "f"(hi));
    return r;
}
__device__ __forceinline__ void fma2(ull& d, ull a, ull b) {
    asm("fma.rn.f32x2 %0, %1, %2, %0;" : "+l"(d) : "l"(a), "l"(b));
}
__device__ __forceinline__ void upk2(ull v, float& lo, float& hi) {
    asm("mov.b64 {%0, %1}, %2;" : "=f"(lo), "=f"(hi) : "l"(v));
}

// ============================================================
// Kernel 0: proj_dec = h @ W  (blocks 0..31) + zero g_score (blocks 32..63)
// ============================================================
__global__ __launch_bounds__(256) void prep_kernel(
    const float* __restrict__ h, const float* __restrict__ W)
{
    const int bid = blockIdx.x;
    const int tid = threadIdx.x;
    if (bid < BB) {
        __shared__ float hs[DD];
        for (int i = tid; i < DD; i += 256) hs[i] = h[bid * DD + i];
        __syncthreads();
        float acc0 = 0.f, acc1 = 0.f, acc2 = 0.f, acc3 = 0.f;
        const int u0 = tid;
        #pragma unroll 4
        for (int d = 0; d < DD; d++) {
            const float hv = hs[d];
            const float* wr = W + (size_t)d * UU + u0;
            acc0 += hv * wr[0];
            acc1 += hv * wr[256];
            acc2 += hv * wr[512];
            acc3 += hv * wr[768];
        }
        g_projdec[bid * UU + u0 + 0]   = acc0;
        g_projdec[bid * UU + u0 + 256] = acc1;
        g_projdec[bid * UU + u0 + 512] = acc2;
        g_projdec[bid * UU + u0 + 768] = acc3;
    } else {
        const int b = bid - BB;
        for (int i = tid; i < SS; i += 256) g_score[b * SS + i] = 0.f;
    }
}

// ============================================================
// Kernel A: fused score GEMM.
// score[b,s] = sum_u V[u] * tanh( (enc[b,s,:] . U[:,u]) + proj_dec[b,u]
//                                  + cov[b,s]*Wcw[u] + Wcb[u] )
// Tile: 128 rows (b,s) x 128 cols (u), k-tile 32. 256 threads, 8x8 per thread.
// Grid: x = u-tile (8, fastest -> L2 reuse of enc row tile), y = row-tile (512).
// Partial V-reduced scores atomicAdd into g_score (8 adds per row total).
// ============================================================
__global__ __launch_bounds__(256) void score_gemm_kernel(
    const float* __restrict__ enc, const float* __restrict__ Umat,
    const float* __restrict__ cov, const float* __restrict__ Wcw,
    const float* __restrict__ Wcb, const float* __restrict__ Vvec)
{
    __shared__ __align__(16) float As[32][132];  // [k][m], padded
    __shared__ __align__(16) float Bs[32][132];  // [k][n], padded

    const int tid = threadIdx.x;
    const int tx = tid & 15;        // n-group
    const int ty = tid >> 4;        // m-group
    const int n0 = blockIdx.x * 128;
    const int rowBase = blockIdx.y * 128;        // global (b,s) row
    const int b = rowBase >> 11;                 // rowBase / S (tile never spans b)

    ull acc[8][4];
    #pragma unroll
    for (int i = 0; i < 8; i++)
        #pragma unroll
        for (int j = 0; j < 4; j++) acc[i][j] = 0ull;

    for (int kt = 0; kt < DD; kt += 32) {
        // Load A tile (128x32) transposed into As[k][m]
        #pragma unroll
        for (int q = tid; q < 1024; q += 256) {
            const int row = q >> 3;
            const int c4 = q & 7;
            float4 v = *(const float4*)(enc + (size_t)(rowBase + row) * DD + kt + (c4 << 2));
            As[(c4 << 2) + 0][row] = v.x;
            As[(c4 << 2) + 1][row] = v.y;
            As[(c4 << 2) + 2][row] = v.z;
            As[(c4 << 2) + 3][row] = v.w;
        }
        // Load B tile (32x128) into Bs[k][n]
        #pragma unroll
        for (int q = tid; q < 1024; q += 256) {
            const int row = q >> 5;
            const int c4 = q & 31;
            *(float4*)(&Bs[row][c4 << 2]) =
                *(const float4*)(Umat + (size_t)(kt + row) * UU + n0 + (c4 << 2));
        }
        __syncthreads();

        #pragma unroll 8
        for (int kk = 0; kk < 32; kk++) {
            const float4 a0 = *(const float4*)&As[kk][(ty << 3) + 0];
            const float4 a1 = *(const float4*)&As[kk][(ty << 3) + 4];
            const float4 b0 = *(const float4*)&Bs[kk][(tx << 3) + 0];
            const float4 b1 = *(const float4*)&Bs[kk][(tx << 3) + 4];
            const ull bp0 = pk2(b0.x, b0.y);
            const ull bp1 = pk2(b0.z, b0.w);
            const ull bp2 = pk2(b1.x, b1.y);
            const ull bp3 = pk2(b1.z, b1.w);
            const float av[8] = {a0.x, a0.y, a0.z, a0.w, a1.x, a1.y, a1.z, a1.w};
            #pragma unroll
            for (int i = 0; i < 8; i++) {
                const ull aa = pk2(av[i], av[i]);
                fma2(acc[i][0], aa, bp0);
                fma2(acc[i][1], aa, bp1);
                fma2(acc[i][2], aa, bp2);
                fma2(acc[i][3], aa, bp3);
            }
        }
        __syncthreads();
    }

    // Epilogue: tanh + V reduction
    float pdn[8], wcn[8], wbn[8], vn[8];
    #pragma unroll
    for (int j = 0; j < 8; j++) {
        const int n = n0 + (tx << 3) + j;
        pdn[j] = g_projdec[b * UU + n];
        wcn[j] = Wcw[n];
        wbn[j] = Wcb[n];
        vn[j] = Vvec[n];
    }
    #pragma unroll
    for (int i = 0; i < 8; i++) {
        const int m = rowBase + (ty << 3) + i;   // global (b,s) row
        const float cv = cov[m];                  // coverage_vector flat [B*S]
        float ps = 0.f;
        #pragma unroll
        for (int j4 = 0; j4 < 4; j4++) {
            float lo, hi;
            upk2(acc[i][j4], lo, hi);
            const int j = j4 * 2;
            ps += tanhf(lo + pdn[j]     + cv * wcn[j]     + wbn[j])     * vn[j];
            ps += tanhf(hi + pdn[j + 1] + cv * wcn[j + 1] + wbn[j + 1]) * vn[j + 1];
        }
        // Reduce across the 16 tx lanes holding this row's n-slices
        ps += __shfl_xor_sync(0xffffffffu, ps, 1);
        ps += __shfl_xor_sync(0xffffffffu, ps, 2);
        ps += __shfl_xor_sync(0xffffffffu, ps, 4);
        ps += __shfl_xor_sync(0xffffffffu, ps, 8);
        if (tx == 0) atomicAdd(&g_score[m], ps);
    }
}

// ============================================================
// Kernel B: per-batch softmax (mask-after collapses to masked softmax),
// writes attention_weights + coverage_out, zeroes context row for K-C atomics.
// ============================================================
__global__ __launch_bounds__(256) void softmax_kernel(
    const float* __restrict__ mask, const float* __restrict__ covin,
    float* __restrict__ out)
{
    const int b = blockIdx.x;
    const int tid = threadIdx.x;
    __shared__ float red[256];

    float loc[8];
    #pragma unroll
    for (int r = 0; r < 8; r++) loc[r] = g_score[b * SS + tid + r * 256];

    float mx = loc[0];
    #pragma unroll
    for (int r = 1; r < 8; r++) mx = fmaxf(mx, loc[r]);
    red[tid] = mx;
    __syncthreads();
    for (int st = 128; st > 0; st >>= 1) {
        if (tid < st) red[tid] = fmaxf(red[tid], red[tid + st]);
        __syncthreads();
    }
    mx = red[0];
    __syncthreads();

    float w[8];
    float lsum = 0.f;
    #pragma unroll
    for (int r = 0; r < 8; r++) {
        const int s = tid + r * 256;
        w[r] = expf(loc[r] - mx) * mask[b * SS + s];
        lsum += w[r];
    }
    red[tid] = lsum;
    __syncthreads();
    for (int st = 128; st > 0; st >>= 1) {
        if (tid < st) red[tid] += red[tid + st];
        __syncthreads();
    }
    const float inv = 1.f / red[0];

    #pragma unroll
    for (int r = 0; r < 8; r++) {
        const int s = tid + r * 256;
        const float a = w[r] * inv;
        out[ATT_OFF + b * SS + s] = a;
        out[COV_OFF + b * SS + s] = covin[b * SS + s] + a;
    }
    // zero the context row for kernel C's atomic accumulation
    for (int i = tid; i < DD; i += 256) out[CTX_OFF + b * DD + i] = 0.f;
}

// ============================================================
// Kernel C: context[b,d] = sum_s attn[b,s] * enc[b,s,d]
// grid (dchunk=4, ssplit=8, b=32), 256 threads, one d per thread.
// ============================================================
__global__ __launch_bounds__(256) void context_kernel(
    const float* __restrict__ enc, float* __restrict__ out)
{
    const int b = blockIdx.z;
    const int d = blockIdx.x * 256 + threadIdx.x;
    const int s0 = blockIdx.y * 256;
    const float* ap = out + ATT_OFF + b * SS + s0;
    const float* ep = enc + ((size_t)(b * SS + s0)) * DD + d;
    float acc = 0.f;
    #pragma unroll 4
    for (int s = 0; s < 256; s++) acc += ap[s] * ep[(size_t)s * DD];
    atomicAdd(&out[CTX_OFF + b * DD + d], acc);
}

// ============================================================
extern "C" void kernel_launch(void* const* d_in, const int* in_sizes, int n_in,
                              void* d_out, int out_size)
{
    const float* enc  = (const float*)d_in[0];  // encoder_outputs [B,S,D]
    const float* mask = (const float*)d_in[1];  // encoder_mask [B,S]
    const float* h    = (const float*)d_in[2];  // decoder_hidden_state [B,D]
    const float* cov  = (const float*)d_in[3];  // coverage_vector [B,S,1,1]
    const float* W    = (const float*)d_in[4];  // [D,U]
    const float* U    = (const float*)d_in[5];  // [D,U]
    const float* Wcw  = (const float*)d_in[6];  // [1,U]
    const float* Wcb  = (const float*)d_in[7];  // [U]
    const float* V    = (const float*)d_in[8];  // [U,1]
    float* out = (float*)d_out;

    prep_kernel<<<64, 256>>>(h, W);
    score_gemm_kernel<<<dim3(8, 512), 256>>>(enc, U, cov, Wcw, Wcb, V);
    softmax_kernel<<<32, 256>>>(mask, cov, out);
    context_kernel<<<dim3(4, 8, 32), 256>>>(enc, out);
}

// round 5
// speedup vs baseline: 1.2863x; 1.2863x over previous
#include <cuda_runtime.h>
#include <math.h>
#include <stdint.h>

// Problem constants
#define BB 32
#define SS 2048
#define DD 1024
#define UU 1024

// d_out layout: [context (32*1024)][attention_weights (32*2048)][coverage_out (32*2048)]
#define CTX_OFF 0
#define ATT_OFF (BB * DD)
#define COV_OFF (BB * DD + BB * SS)

// Score GEMM tiling (static smem <= 48KB: BK=16, double buffer)
#define BM 128
#define BN 128
#define BK 16
#define NK (DD / BK)      // 64 k-tiles
#define AS_STR 20         // A smem row stride (floats): 8 gid-rows hit distinct bank groups
#define BS_STR 136        // B smem row stride (floats), conflict-free
#define STAGE_FLOATS (BM * AS_STR + BK * BS_STR)   // 2560 + 2176 = 4736
// total static smem = 2 * 4736 * 4 = 37,888 B  (< 48 KB, no opt-in needed)

// Scratch (allocation-free per harness rules)
__device__ float g_projdec[BB * UU];
__device__ float g_score[BB * SS];

// ---------------- helpers ----------------
__device__ __forceinline__ void cpasync16(void* smem_dst, const void* gmem_src) {
    uint32_t s = (uint32_t)__cvta_generic_to_shared(smem_dst);
    asm volatile("cp.async.cg.shared.global [%0], [%1], 16;\n" :: "r"(s), "l"(gmem_src));
}
__device__ __forceinline__ void cp_commit() {
    asm volatile("cp.async.commit_group;\n" ::);
}
template <int N>
__device__ __forceinline__ void cp_wait() {
    asm volatile("cp.async.wait_group %0;\n" :: "n"(N));
}
// Split fp32 into hi/lo tf32 (3xTF32 trick)
__device__ __forceinline__ void split_tf32(float x, uint32_t& hi, uint32_t& lo) {
    asm("cvt.rna.tf32.f32 %0, %1;" : "=r"(hi) : "f"(x));
    float r = x - __uint_as_float(hi);
    asm("cvt.rna.tf32.f32 %0, %1;" : "=r"(lo) : "f"(r));
}
__device__ __forceinline__ void mma_tf32(float* d, const uint32_t* a, const uint32_t* b) {
    asm volatile(
        "mma.sync.aligned.m16n8k8.row.col.f32.tf32.tf32.f32 "
        "{%0,%1,%2,%3}, {%4,%5,%6,%7}, {%8,%9}, {%0,%1,%2,%3};\n"
        : "+f"(d[0]), "+f"(d[1]), "+f"(d[2]), "+f"(d[3])
        : "r"(a[0]), "r"(a[1]), "r"(a[2]), "r"(a[3]), "r"(b[0]), "r"(b[1]));
}
// Fast accurate tanh: 2 MUFU (ex2 + rcp). Exact at +/-inf, abs err ~1e-7.
__device__ __forceinline__ float tanh_fast(float x) {
    float e = __expf(2.f * x);
    return 1.f - __fdividef(2.f, e + 1.f);
}

// ============================================================
// Kernel 0: proj_dec = h @ W  (blocks 0..31) + zero g_score (blocks 32..63)
// ============================================================
__global__ __launch_bounds__(256) void prep_kernel(
    const float* __restrict__ h, const float* __restrict__ W)
{
    const int bid = blockIdx.x;
    const int tid = threadIdx.x;
    if (bid < BB) {
        __shared__ float hs[DD];
        for (int i = tid; i < DD; i += 256) hs[i] = h[bid * DD + i];
        __syncthreads();
        float acc0 = 0.f, acc1 = 0.f, acc2 = 0.f, acc3 = 0.f;
        const int u0 = tid;
        #pragma unroll 4
        for (int d = 0; d < DD; d++) {
            const float hv = hs[d];
            const float* wr = W + (size_t)d * UU + u0;
            acc0 += hv * wr[0];
            acc1 += hv * wr[256];
            acc2 += hv * wr[512];
            acc3 += hv * wr[768];
        }
        g_projdec[bid * UU + u0 + 0]   = acc0;
        g_projdec[bid * UU + u0 + 256] = acc1;
        g_projdec[bid * UU + u0 + 512] = acc2;
        g_projdec[bid * UU + u0 + 768] = acc3;
    } else {
        const int b = bid - BB;
        for (int i = tid; i < SS; i += 256) g_score[b * SS + i] = 0.f;
    }
}

// ============================================================
// Kernel A: fused score GEMM on tensor cores (3xTF32 mma.sync m16n8k8).
// score[b,s] = sum_u V[u]*tanh( enc[b,s,:].U[:,u] + proj_dec[b,u] + cov*Wcw[u] + Wcb[u] )
// CTA tile 128x128, BK=16, double-buffered cp.async, static smem 37.9KB.
// 8 warps = 4(m) x 2(n), warp tile 32x64 = 2 m16-tiles x 8 n8-tiles.
// ============================================================
__global__ __launch_bounds__(256) void score_gemm_kernel(
    const float* __restrict__ enc, const float* __restrict__ Umat,
    const float* __restrict__ cov, const float* __restrict__ Wcw,
    const float* __restrict__ Wcb, const float* __restrict__ Vvec)
{
    __shared__ __align__(16) float smem[2 * STAGE_FLOATS];

    const int tid = threadIdx.x;
    const int wid = tid >> 5;
    const int lane = tid & 31;
    const int gid = lane >> 2;      // 0..7
    const int tig = lane & 3;       // 0..3
    const int wm = wid >> 1;        // 0..3  (m direction)
    const int wn = wid & 1;         // 0..1  (n direction)

    const int n0 = blockIdx.x * BN;
    const int rowBase = blockIdx.y * BM;
    const int b = rowBase >> 11;    // tile never spans a batch

    float acc[2][8][4];
    #pragma unroll
    for (int mt = 0; mt < 2; mt++)
        #pragma unroll
        for (int nt = 0; nt < 8; nt++)
            #pragma unroll
            for (int q = 0; q < 4; q++) acc[mt][nt][q] = 0.f;

    // ---- stage loader: A 128x16 (512 float4), B 16x128 (512 float4) ----
    auto load_stage = [&](int stage, int kt) {
        float* As = smem + stage * STAGE_FLOATS;
        float* Bs = As + BM * AS_STR;
        const float* ga = enc + (size_t)rowBase * DD + kt * BK;
        #pragma unroll
        for (int p = 0; p < 2; p++) {
            int idx = tid + p * 256;
            int r = idx >> 2, c = idx & 3;       // 128 rows x 4 float4
            cpasync16(As + r * AS_STR + c * 4, ga + (size_t)r * DD + c * 4);
        }
        const float* gb = Umat + (size_t)(kt * BK) * UU + n0;
        #pragma unroll
        for (int p = 0; p < 2; p++) {
            int idx = tid + p * 256;
            int r = idx >> 5, c = idx & 31;      // 16 rows x 32 float4
            cpasync16(Bs + r * BS_STR + c * 4, gb + (size_t)r * UU + c * 4);
        }
    };

    load_stage(0, 0); cp_commit();

    for (int kt = 0; kt < NK; kt++) {
        if (kt + 1 < NK) {
            load_stage((kt + 1) & 1, kt + 1); cp_commit();
            cp_wait<1>();   // tile kt resident, tile kt+1 in flight
        } else {
            cp_wait<0>();
        }
        __syncthreads();

        const float* As = smem + (kt & 1) * STAGE_FLOATS;
        const float* Bs = As + BM * AS_STR;

        #pragma unroll
        for (int k8 = 0; k8 < BK / 8; k8++) {
            const int kk = k8 * 8;
            uint32_t ah[2][4], al[2][4], bh[8][2], bl[8][2];
            #pragma unroll
            for (int mt = 0; mt < 2; mt++) {
                const int r0 = wm * 32 + mt * 16 + gid;
                split_tf32(As[(r0)     * AS_STR + kk + tig],     ah[mt][0], al[mt][0]);
                split_tf32(As[(r0 + 8) * AS_STR + kk + tig],     ah[mt][1], al[mt][1]);
                split_tf32(As[(r0)     * AS_STR + kk + tig + 4], ah[mt][2], al[mt][2]);
                split_tf32(As[(r0 + 8) * AS_STR + kk + tig + 4], ah[mt][3], al[mt][3]);
            }
            #pragma unroll
            for (int nt = 0; nt < 8; nt++) {
                const int c0 = wn * 64 + nt * 8 + gid;
                split_tf32(Bs[(kk + tig)     * BS_STR + c0], bh[nt][0], bl[nt][0]);
                split_tf32(Bs[(kk + tig + 4) * BS_STR + c0], bh[nt][1], bl[nt][1]);
            }
            #pragma unroll
            for (int mt = 0; mt < 2; mt++) {
                #pragma unroll
                for (int nt = 0; nt < 8; nt++) {
                    mma_tf32(acc[mt][nt], al[mt], bh[nt]);   // lo*hi
                    mma_tf32(acc[mt][nt], ah[mt], bl[nt]);   // hi*lo
                    mma_tf32(acc[mt][nt], ah[mt], bh[nt]);   // hi*hi
                }
            }
        }
        __syncthreads();   // readers done before next-next load overwrites this stage
    }

    // ---- epilogue: tanh + V reduction, atomic into g_score ----
    float cv[2][2];
    int mrow[2][2];
    #pragma unroll
    for (int mt = 0; mt < 2; mt++)
        #pragma unroll
        for (int ro = 0; ro < 2; ro++) {
            mrow[mt][ro] = rowBase + wm * 32 + mt * 16 + ro * 8 + gid;
            cv[mt][ro] = cov[mrow[mt][ro]];
        }

    float ps[2][2] = {{0.f, 0.f}, {0.f, 0.f}};
    #pragma unroll
    for (int nt = 0; nt < 8; nt++) {
        #pragma unroll
        for (int j = 0; j < 2; j++) {
            const int n = n0 + wn * 64 + nt * 8 + 2 * tig + j;
            const float pd = g_projdec[b * UU + n];
            const float wc_ = Wcw[n];
            const float wb = Wcb[n];
            const float v = Vvec[n];
            #pragma unroll
            for (int mt = 0; mt < 2; mt++)
                #pragma unroll
                for (int ro = 0; ro < 2; ro++) {
                    const float x = acc[mt][nt][2 * ro + j] + pd + cv[mt][ro] * wc_ + wb;
                    ps[mt][ro] += tanh_fast(x) * v;
                }
        }
    }
    // reduce over the 4 tig lanes sharing each row
    #pragma unroll
    for (int mt = 0; mt < 2; mt++)
        #pragma unroll
        for (int ro = 0; ro < 2; ro++) {
            float s = ps[mt][ro];
            s += __shfl_xor_sync(0xffffffffu, s, 1);
            s += __shfl_xor_sync(0xffffffffu, s, 2);
            if (tig == 0) atomicAdd(&g_score[mrow[mt][ro]], s);
        }
}

// ============================================================
// Kernel B: per-batch masked softmax + coverage, zero context rows.
// ============================================================
__global__ __launch_bounds__(256) void softmax_kernel(
    const float* __restrict__ mask, const float* __restrict__ covin,
    float* __restrict__ out)
{
    const int b = blockIdx.x;
    const int tid = threadIdx.x;
    __shared__ float red[256];

    float loc[8];
    #pragma unroll
    for (int r = 0; r < 8; r++) loc[r] = g_score[b * SS + tid + r * 256];

    float mx = loc[0];
    #pragma unroll
    for (int r = 1; r < 8; r++) mx = fmaxf(mx, loc[r]);
    red[tid] = mx;
    __syncthreads();
    for (int st = 128; st > 0; st >>= 1) {
        if (tid < st) red[tid] = fmaxf(red[tid], red[tid + st]);
        __syncthreads();
    }
    mx = red[0];
    __syncthreads();

    float w[8];
    float lsum = 0.f;
    #pragma unroll
    for (int r = 0; r < 8; r++) {
        const int s = tid + r * 256;
        w[r] = expf(loc[r] - mx) * mask[b * SS + s];
        lsum += w[r];
    }
    red[tid] = lsum;
    __syncthreads();
    for (int st = 128; st > 0; st >>= 1) {
        if (tid < st) red[tid] += red[tid + st];
        __syncthreads();
    }
    const float inv = 1.f / red[0];

    #pragma unroll
    for (int r = 0; r < 8; r++) {
        const int s = tid + r * 256;
        const float a = w[r] * inv;
        out[ATT_OFF + b * SS + s] = a;
        out[COV_OFF + b * SS + s] = covin[b * SS + s] + a;
    }
    for (int i = tid; i < DD; i += 256) out[CTX_OFF + b * DD + i] = 0.f;
}

// ============================================================
// Kernel C: context[b,d] = sum_s attn[b,s] * enc[b,s,d]
// grid (4, 16, 32), s-chunk 128, one d per thread, atomic accumulate.
// ============================================================
__global__ __launch_bounds__(256) void context_kernel(
    const float* __restrict__ enc, float* __restrict__ out)
{
    const int b = blockIdx.z;
    const int d = blockIdx.x * 256 + threadIdx.x;
    const int s0 = blockIdx.y * 128;
    const float* ap = out + ATT_OFF + b * SS + s0;
    const float* ep = enc + ((size_t)(b * SS + s0)) * DD + d;
    float acc = 0.f;
    #pragma unroll 8
    for (int s = 0; s < 128; s++) acc += ap[s] * ep[(size_t)s * DD];
    atomicAdd(&out[CTX_OFF + b * DD + d], acc);
}

// ============================================================
extern "C" void kernel_launch(void* const* d_in, const int* in_sizes, int n_in,
                              void* d_out, int out_size)
{
    const float* enc  = (const float*)d_in[0];  // encoder_outputs [B,S,D]
    const float* mask = (const float*)d_in[1];  // encoder_mask [B,S]
    const float* h    = (const float*)d_in[2];  // decoder_hidden_state [B,D]
    const float* cov  = (const float*)d_in[3];  // coverage_vector [B,S,1,1]
    const float* W    = (const float*)d_in[4];  // [D,U]
    const float* U    = (const float*)d_in[5];  // [D,U]
    const float* Wcw  = (const float*)d_in[6];  // [1,U]
    const float* Wcb  = (const float*)d_in[7];  // [U]
    const float* V    = (const float*)d_in[8];  // [U,1]
    float* out = (float*)d_out;

    prep_kernel<<<64, 256>>>(h, W);
    score_gemm_kernel<<<dim3(8, 512), 256>>>(enc, U, cov, Wcw, Wcb, V);
    softmax_kernel<<<32, 256>>>(mask, cov, out);
    context_kernel<<<dim3(4, 16, 32), 256>>>(enc, out);
}